// round 15
// baseline (speedup 1.0000x reference)
#include <cuda_runtime.h>
#include <cstdint>

namespace {
constexpr int  CIN  = 16;
constexpr int  COUT = 16;
constexpr int  KS   = 4;
constexpr long long NN = 524288;
constexpr int  THREADS = 128;                 // 4 warps
constexpr int  GRID    = 8192;
constexpr int  NWARPS  = GRID * 4;            // 32768 warps
constexpr int  NBLK    = (int)(8 * NN / 32);  // 131072 32-token blocks
constexpr int  PER_W   = NBLK / NWARPS;       // 4 blocks per warp
}

__device__ __forceinline__ unsigned long long fma2(unsigned long long a,
                                                   unsigned long long b,
                                                   unsigned long long c) {
    unsigned long long d;
    asm("fma.rn.f32x2 %0, %1, %2, %3;" : "=l"(d) : "l"(a), "l"(b), "l"(c));
    return d;
}
__device__ __forceinline__ unsigned long long pack2(float lo, float hi) {
    unsigned long long d;
    asm("mov.b64 %0, {%1, %2};" : "=l"(d) : "f"(lo), "f"(hi));
    return d;
}
// pack two f32 -> bf16x2 rn. First operand = HIGH half (element 1).
__device__ __forceinline__ uint32_t packbf(float hi, float lo) {
    uint32_t r;
    asm("cvt.rn.bf16x2.f32 %0, %1, %2;" : "=r"(r) : "f"(hi), "f"(lo));
    return r;
}
// m16n8k16 row.col bf16 MMA, accumulate in place. A = weights (regs).
__device__ __forceinline__ void mma_bf16(float* d, const uint32_t* a,
                                         uint32_t b0, uint32_t b1) {
    asm volatile(
        "mma.sync.aligned.m16n8k16.row.col.f32.bf16.bf16.f32 "
        "{%0,%1,%2,%3}, {%4,%5,%6,%7}, {%8,%9}, {%0,%1,%2,%3};"
        : "+f"(d[0]), "+f"(d[1]), "+f"(d[2]), "+f"(d[3])
        : "r"(a[0]), "r"(a[1]), "r"(a[2]), "r"(a[3]), "r"(b0), "r"(b1));
}
__device__ __forceinline__ float u64lo(unsigned long long v) {
    return __uint_as_float((uint32_t)v);
}
__device__ __forceinline__ float u64hi(unsigned long long v) {
    return __uint_as_float((uint32_t)(v >> 32));
}
// split a channel-pair (x0=c even, x1=c odd) into bf16x2 hi + lo
__device__ __forceinline__ void split_pair(float x0, float x1,
                                           uint32_t& hp, uint32_t& lp) {
    hp = packbf(x1, x0);
    float f0 = __uint_as_float(hp << 16);
    float f1 = __uint_as_float(hp & 0xFFFF0000u);
    lp = packbf(x1 - f1, x0 - f0);
}

// R15: ZERO shared memory. All fragments gathered directly from gmem
// (x: 16 LDG.32/block, s: 16 LDG.64/block, L1/L2 resident). Removes the
// LDG->STS->LDS staging round-trip whose smem-crossbar cycles (LDS eff-4cyc
// at nw>=4) were ~50% of runtime. No barriers at all.
__global__ __launch_bounds__(THREADS, 4)
void tconv_mma_kernel(const float* __restrict__ inp,   // [B, CIN, N]
                      const float* __restrict__ wgt,   // [COUT, KS, CIN]
                      const float* __restrict__ att,   // [B, KS, N]
                      float* __restrict__ out)         // [B, COUT, N]
{
    const int tid  = threadIdx.x;
    const int lane = tid & 31;
    const int w    = tid >> 5;
    const int cq   = lane & 3;
    const int r    = lane >> 2;
    const unsigned FULL = 0xFFFFFFFFu;

    // ---- W as A-fragments, built once (split hi/lo) ----
    uint32_t ah[KS][4], al[KS][4];
    #pragma unroll
    for (int kt = 0; kt < KS; kt++) {
        #pragma unroll
        for (int idx = 0; idx < 4; idx++) {
            int o  = r + 8 * (idx & 1);
            int cb = 2 * cq + 8 * (idx >> 1);
            float wa = wgt[(o * KS + kt) * CIN + cb];
            float wb = wgt[(o * KS + kt) * CIN + cb + 1];
            split_pair(wa, wb, ah[kt][idx], al[kt][idx]);
        }
    }

    const int wg = blockIdx.x * 4 + w;            // global warp id

    // x fragment gather for one block: 4 tiles (token off = 8*t), 4 channels.
    // xf[t][0..3] = x[2cq], x[2cq+1], x[2cq+8], x[2cq+9] at token off+r.
    auto loadx = [&](int blk, float xf[4][4]) {
        long long b  = blk >> 14;                  // NN/32 = 16384
        long long n0 = ((long long)(blk & 16383)) << 5;
        const float* base = inp + b * CIN * NN + n0 + r;
        #pragma unroll
        for (int t = 0; t < 4; t++) {
            #pragma unroll
            for (int j = 0; j < 4; j++) {
                int ch = 2 * cq + (j & 1) + 8 * (j >> 1);
                xf[t][j] = base[(long long)ch * NN + 8 * t];
            }
        }
    };

    float xf[4][4];
    loadx(wg, xf);

    #pragma unroll 1
    for (int i = 0; i < PER_W; i++) {
        const int blk = wg + i * NWARPS;
        const long long b  = blk >> 14;
        const long long n0 = ((long long)(blk & 16383)) << 5;

        // split current block into bf16 fragments (registers only)
        uint32_t bh[4][2], bl[4][2];
        #pragma unroll
        for (int t = 0; t < 4; t++) {
            split_pair(xf[t][0], xf[t][1], bh[t][0], bl[t][0]);
            split_pair(xf[t][2], xf[t][3], bh[t][1], bl[t][1]);
        }

        // prefetch next block's x
        if (i + 1 < PER_W) loadx(wg + (i + 1) * NWARPS, xf);

        const float* sbase = att + b * KS * NN + n0 + 2 * cq;
        float* ob = out + b * COUT * NN + n0;

        #pragma unroll
        for (int jp = 0; jp < 2; jp++) {
            const int tb0 = jp * 16;
            const int tA = jp * 2, tB = jp * 2 + 1;

            // s pairs direct from gmem: (s[tok], s[tok+1]) as u64, tok = tb0(+8)+2cq
            unsigned long long s2A[KS], s2B[KS];
            #pragma unroll
            for (int kt = 0; kt < KS; kt++) {
                s2A[kt] = *reinterpret_cast<const unsigned long long*>(
                    sbase + (long long)kt * NN + tb0);
                s2B[kt] = *reinterpret_cast<const unsigned long long*>(
                    sbase + (long long)kt * NN + tb0 + 8);
            }

            unsigned long long yA0, yA1, yB0, yB1;
            // ===== n8 tile A =====
            {
                float dG[KS][4] = {};
                #pragma unroll
                for (int kt = 0; kt < KS; kt++) {
                    mma_bf16(dG[kt], ah[kt], bh[tA][0], bh[tA][1]);
                    mma_bf16(dG[kt], ah[kt], bl[tA][0], bl[tA][1]);
                    mma_bf16(dG[kt], al[kt], bh[tA][0], bh[tA][1]);
                }
                yA0 = 0ull; yA1 = 0ull;
                #pragma unroll
                for (int kt = 0; kt < KS; kt++) {
                    yA0 = fma2(pack2(dG[kt][0], dG[kt][1]), s2A[kt], yA0);
                    yA1 = fma2(pack2(dG[kt][2], dG[kt][3]), s2A[kt], yA1);
                }
            }
            // ===== n8 tile B =====
            {
                float dG[KS][4] = {};
                #pragma unroll
                for (int kt = 0; kt < KS; kt++) {
                    mma_bf16(dG[kt], ah[kt], bh[tB][0], bh[tB][1]);
                    mma_bf16(dG[kt], ah[kt], bl[tB][0], bl[tB][1]);
                    mma_bf16(dG[kt], al[kt], bh[tB][0], bh[tB][1]);
                }
                yB0 = 0ull; yB1 = 0ull;
                #pragma unroll
                for (int kt = 0; kt < KS; kt++) {
                    yB0 = fma2(pack2(dG[kt][0], dG[kt][1]), s2B[kt], yB0);
                    yB1 = fma2(pack2(dG[kt][2], dG[kt][3]), s2B[kt], yB1);
                }
            }

            // ===== composed stores (proven mapping) =====
            unsigned long long eA0 = __shfl_xor_sync(FULL, yA0, 1);
            unsigned long long eA1 = __shfl_xor_sync(FULL, yA1, 1);
            unsigned long long eB0 = __shfl_xor_sync(FULL, yB0, 1);
            unsigned long long eB1 = __shfl_xor_sync(FULL, yB1, 1);

            const int off = ((cq & 1) << 3) | ((cq >> 1) << 2);
            float4 v0, v1;
            if ((cq & 1) == 0) {
                v0 = make_float4(u64lo(yA0), u64hi(yA0), u64lo(eA0), u64hi(eA0));
                v1 = make_float4(u64lo(yA1), u64hi(yA1), u64lo(eA1), u64hi(eA1));
            } else {
                v0 = make_float4(u64lo(eB0), u64hi(eB0), u64lo(yB0), u64hi(yB0));
                v1 = make_float4(u64lo(eB1), u64hi(eB1), u64lo(yB1), u64hi(yB1));
            }
            *reinterpret_cast<float4*>(ob + (long long)r       * NN + tb0 + off) = v0;
            *reinterpret_cast<float4*>(ob + (long long)(r + 8) * NN + tb0 + off) = v1;
        }
    }
}

extern "C" void kernel_launch(void* const* d_in, const int* in_sizes, int n_in,
                              void* d_out, int out_size)
{
    const float* inp = (const float*)d_in[0];   // input  [8,16,524288]
    const float* wgt = (const float*)d_in[1];   // weight [16,4,16]
    const float* att = (const float*)d_in[2];   // attention_score [8,4,524288]
    float* out = (float*)d_out;                 // [8,16,524288]

    tconv_mma_kernel<<<GRID, THREADS>>>(inp, wgt, att, out);
}

// round 16
// speedup vs baseline: 1.3888x; 1.3888x over previous
#include <cuda_runtime.h>
#include <cstdint>

namespace {
constexpr int  CIN  = 16;
constexpr int  COUT = 16;
constexpr int  KS   = 4;
constexpr long long NN = 524288;
constexpr int  THREADS = 128;                 // 4 warps
constexpr int  TOK     = 128;                 // tokens per CTA-tile
constexpr int  TILES   = (int)(8 * NN / TOK); // 32768
constexpr int  GRID    = 8192;                // 4 tiles per CTA
constexpr int  PER_CTA = TILES / GRID;        // 4
constexpr int  PADT    = 132;                 // x row pitch (f32 words)
constexpr int  PS      = 132;                 // s row pitch
}

__device__ __forceinline__ unsigned long long fma2(unsigned long long a,
                                                   unsigned long long b,
                                                   unsigned long long c) {
    unsigned long long d;
    asm("fma.rn.f32x2 %0, %1, %2, %3;" : "=l"(d) : "l"(a), "l"(b), "l"(c));
    return d;
}
__device__ __forceinline__ unsigned long long pack2(float lo, float hi) {
    unsigned long long d;
    asm("mov.b64 %0, {%1, %2};" : "=l"(d) : "f"(lo), "f"(hi));
    return d;
}
// pack two f32 -> bf16x2 rn. First operand = HIGH half (element 1).
__device__ __forceinline__ uint32_t packbf(float hi, float lo) {
    uint32_t r;
    asm("cvt.rn.bf16x2.f32 %0, %1, %2;" : "=r"(r) : "f"(hi), "f"(lo));
    return r;
}
// m16n8k16 row.col bf16 MMA, accumulate in place. A = weights (regs).
__device__ __forceinline__ void mma_bf16(float* d, const uint32_t* a,
                                         uint32_t b0, uint32_t b1) {
    asm volatile(
        "mma.sync.aligned.m16n8k16.row.col.f32.bf16.bf16.f32 "
        "{%0,%1,%2,%3}, {%4,%5,%6,%7}, {%8,%9}, {%0,%1,%2,%3};"
        : "+f"(d[0]), "+f"(d[1]), "+f"(d[2]), "+f"(d[3])
        : "r"(a[0]), "r"(a[1]), "r"(a[2]), "r"(a[3]), "r"(b0), "r"(b1));
}
__device__ __forceinline__ float u64lo(unsigned long long v) {
    return __uint_as_float((uint32_t)v);
}
__device__ __forceinline__ float u64hi(unsigned long long v) {
    return __uint_as_float((uint32_t)(v >> 32));
}
// split a channel pair (x0 even-c, x1 odd-c) into bf16x2 hi + lo
__device__ __forceinline__ void split_pair(float x0, float x1,
                                           uint32_t& hp, uint32_t& lp) {
    hp = packbf(x1, x0);
    float f0 = __uint_as_float(hp << 16);
    float f1 = __uint_as_float(hp & 0xFFFF0000u);
    lp = packbf(x1 - f1, x0 - f0);
}
__device__ __forceinline__ uint32_t smem_u32(const void* p) {
    uint32_t a;
    asm("{ .reg .u64 t; cvta.to.shared.u64 t, %1; cvt.u32.u64 %0, t; }"
        : "=r"(a) : "l"(p));
    return a;
}
#define CP_ASYNC16(dst, src) \
    asm volatile("cp.async.cg.shared.global [%0], [%1], 16;" \
                 :: "r"(dst), "l"(src) : "memory")
#define CP_COMMIT()  asm volatile("cp.async.commit_group;" ::: "memory")
#define CP_WAIT1()   asm volatile("cp.async.wait_group 1;" ::: "memory")

// R16: R11 compute core + cp.async.cg staging (no LDG->reg->STS round trip,
// L1 bypass on loads, ~20 fewer registers -> 6 CTAs/SM).
__global__ __launch_bounds__(THREADS, 6)
void tconv_mma_kernel(const float* __restrict__ inp,   // [B, CIN, N]
                      const float* __restrict__ wgt,   // [COUT, KS, CIN]
                      const float* __restrict__ att,   // [B, KS, N]
                      float* __restrict__ out)         // [B, COUT, N]
{
    // raw f32 staging, double-buffered: x [c][tok] (16 x 132), s [k][tok]
    __shared__ __align__(16) float xs[2][CIN * PADT];
    __shared__ __align__(16) float ssm[2][KS * PS];

    const int tid  = threadIdx.x;
    const int lane = tid & 31;
    const int w    = tid >> 5;
    const int cq   = lane & 3;
    const int r    = lane >> 2;
    const unsigned FULL = 0xFFFFFFFFu;

    // ---- W as A-fragments, built once (split hi/lo) ----
    uint32_t ah[KS][4], al[KS][4];
    #pragma unroll
    for (int kt = 0; kt < KS; kt++) {
        #pragma unroll
        for (int idx = 0; idx < 4; idx++) {
            int o  = r + 8 * (idx & 1);
            int cb = 2 * cq + 8 * (idx >> 1);
            float wa = wgt[(o * KS + kt) * CIN + cb];
            float wb = wgt[(o * KS + kt) * CIN + cb + 1];
            split_pair(wa, wb, ah[kt][idx], al[kt][idx]);
        }
    }

    // issue one tile's staging via cp.async (each thread: 4 x-chunks + 1 s-chunk)
    auto issue_tile = [&](int t, int buf) {
        long long b  = t >> 12;
        long long n0 = ((long long)(t & 4095)) << 7;
        uint32_t xdst = smem_u32(&xs[buf][0]);
        uint32_t sdst = smem_u32(&ssm[buf][0]);
        #pragma unroll
        for (int m = 0; m < 4; m++) {
            int c = w + 4 * m;                  // warps cover rows 0..15
            const float* src = inp + (b * CIN + c) * NN + n0 + 4 * lane;
            CP_ASYNC16(xdst + (uint32_t)(c * PADT + 4 * lane) * 4u, src);
        }
        const float* ssrc = att + (b * KS + w) * NN + n0 + 4 * lane;
        CP_ASYNC16(sdst + (uint32_t)(w * PS + 4 * lane) * 4u, ssrc);
    };

    // prologue: stage tile 0
    issue_tile(blockIdx.x, 0);
    CP_COMMIT();

    #pragma unroll 1
    for (int i = 0; i < PER_CTA; i++) {
        const int t = blockIdx.x + i * GRID;

        // issue tile i+1 into the other buffer (always commit to keep group count)
        if (i + 1 < PER_CTA) issue_tile(t + GRID, (i + 1) & 1);
        CP_COMMIT();
        CP_WAIT1();            // tile i's group complete
        __syncthreads();

        const float* xb = xs[i & 1];
        const float* sb = ssm[i & 1];
        const long long bb = t >> 12;
        const long long n0 = ((long long)(t & 4095)) << 7;
        float* ob = out + bb * COUT * NN + n0;

        #pragma unroll
        for (int jp = 0; jp < 2; jp++) {
            const int tb0 = w * 32 + jp * 16;
            const int tb1 = tb0 + 8;
            unsigned long long yA0, yA1, yB0, yB1;

            // ===== n8 tile A (tokens tb0..tb0+7) =====
            {
                const int tA = tb0 + r;
                float x0 = xb[(2 * cq)     * PADT + tA];
                float x1 = xb[(2 * cq + 1) * PADT + tA];
                float x8 = xb[(2 * cq + 8) * PADT + tA];
                float x9 = xb[(2 * cq + 9) * PADT + tA];
                uint32_t bh0, bl0, bh1, bl1;
                split_pair(x0, x1, bh0, bl0);
                split_pair(x8, x9, bh1, bl1);
                float dG[KS][4] = {};
                #pragma unroll
                for (int kt = 0; kt < KS; kt++) {
                    mma_bf16(dG[kt], ah[kt], bh0, bh1);
                    mma_bf16(dG[kt], ah[kt], bl0, bl1);
                    mma_bf16(dG[kt], al[kt], bh0, bh1);
                }
                yA0 = 0ull; yA1 = 0ull;
                #pragma unroll
                for (int kt = 0; kt < KS; kt++) {
                    unsigned long long s2 = *reinterpret_cast<const unsigned long long*>(
                        sb + kt * PS + tb0 + 2 * cq);
                    yA0 = fma2(pack2(dG[kt][0], dG[kt][1]), s2, yA0);
                    yA1 = fma2(pack2(dG[kt][2], dG[kt][3]), s2, yA1);
                }
            }
            // ===== n8 tile B (tokens tb1..tb1+7) =====
            {
                const int tB = tb1 + r;
                float x0 = xb[(2 * cq)     * PADT + tB];
                float x1 = xb[(2 * cq + 1) * PADT + tB];
                float x8 = xb[(2 * cq + 8) * PADT + tB];
                float x9 = xb[(2 * cq + 9) * PADT + tB];
                uint32_t bh0, bl0, bh1, bl1;
                split_pair(x0, x1, bh0, bl0);
                split_pair(x8, x9, bh1, bl1);
                float dG[KS][4] = {};
                #pragma unroll
                for (int kt = 0; kt < KS; kt++) {
                    mma_bf16(dG[kt], ah[kt], bh0, bh1);
                    mma_bf16(dG[kt], ah[kt], bl0, bl1);
                    mma_bf16(dG[kt], al[kt], bh0, bh1);
                }
                yB0 = 0ull; yB1 = 0ull;
                #pragma unroll
                for (int kt = 0; kt < KS; kt++) {
                    unsigned long long s2 = *reinterpret_cast<const unsigned long long*>(
                        sb + kt * PS + tb1 + 2 * cq);
                    yB0 = fma2(pack2(dG[kt][0], dG[kt][1]), s2, yB0);
                    yB1 = fma2(pack2(dG[kt][2], dG[kt][3]), s2, yB1);
                }
            }

            // ===== composed stores (proven mapping) =====
            unsigned long long eA0 = __shfl_xor_sync(FULL, yA0, 1);
            unsigned long long eA1 = __shfl_xor_sync(FULL, yA1, 1);
            unsigned long long eB0 = __shfl_xor_sync(FULL, yB0, 1);
            unsigned long long eB1 = __shfl_xor_sync(FULL, yB1, 1);

            const int off = ((cq & 1) << 3) | ((cq >> 1) << 2);
            float4 v0, v1;
            if ((cq & 1) == 0) {
                v0 = make_float4(u64lo(yA0), u64hi(yA0), u64lo(eA0), u64hi(eA0));
                v1 = make_float4(u64lo(yA1), u64hi(yA1), u64lo(eA1), u64hi(eA1));
            } else {
                v0 = make_float4(u64lo(eB0), u64hi(eB0), u64lo(yB0), u64hi(yB0));
                v1 = make_float4(u64lo(eB1), u64hi(eB1), u64lo(yB1), u64hi(yB1));
            }
            *reinterpret_cast<float4*>(ob + (long long)r       * NN + tb0 + off) = v0;
            *reinterpret_cast<float4*>(ob + (long long)(r + 8) * NN + tb0 + off) = v1;
        }
        __syncthreads();   // all warps done with buf (i&1) before it is re-staged
    }
}

extern "C" void kernel_launch(void* const* d_in, const int* in_sizes, int n_in,
                              void* d_out, int out_size)
{
    const float* inp = (const float*)d_in[0];   // input  [8,16,524288]
    const float* wgt = (const float*)d_in[1];   // weight [16,4,16]
    const float* att = (const float*)d_in[2];   // attention_score [8,4,524288]
    float* out = (float*)d_out;                 // [8,16,524288]

    tconv_mma_kernel<<<GRID, THREADS>>>(inp, wgt, att, out);
}